// round 1
// baseline (speedup 1.0000x reference)
#include <cuda_runtime.h>
#include <cuda_bf16.h>

#define NA 51   // n_atom

// Scratch for deterministic two-stage loss reduction (no cudaMalloc allowed).
__device__ float g_partials[4096];

__global__ __launch_bounds__(1024, 2) void dtd_kernel(
    const float* __restrict__ dist,          // (B, N, NA)
    const float* __restrict__ next_n_dist,   // (B, N, NA)
    const int*   __restrict__ action,        // (B,)
    const int*   __restrict__ next_n_action, // (B,)
    const float* __restrict__ reward,        // (T, B)
    const unsigned int* __restrict__ done,   // (B,) -- int32 or float32 encoded bool; !=0 test works for both
    const float* __restrict__ weight,        // (B,)
    const float* __restrict__ gamma_p,
    const float* __restrict__ vmin_p,
    const float* __restrict__ vmax_p,
    float* __restrict__ td_out,              // (B,)
    int B, int N, int T)
{
    __shared__ float slog[32][NA + 1];  // per-warp log p row
    __shared__ float s_td[32];
    __shared__ float s_w[32];

    const int warp = threadIdx.x >> 5;
    const int lane = threadIdx.x & 31;
    const int b    = blockIdx.x * 32 + warp;

    float acc = 0.0f;

    if (b < B) {
        const float gamma = *gamma_p;
        const float v_min = *vmin_p;
        const float v_max = *vmax_p;
        const float dz     = (v_max - v_min) * (1.0f / (float)(NA - 1));
        const float inv_dz = (float)(NA - 1) / (v_max - v_min);

        // n-step discounted reward: r = sum_t gamma^t * reward[t, b]
        float r = 0.0f, gf = 1.0f;
        for (int t = 0; t < T; t++) {
            r += gf * __ldg(&reward[(long long)t * B + b]);
            gf *= gamma;
        }
        // gf == gamma^T now
        const float gTnd = (done[b] != 0u) ? 0.0f : gf;

        const long long rowp = ((long long)b * N + action[b]) * NA;
        const long long rowt = ((long long)b * N + next_n_action[b]) * NA;
        const float* prow = dist        + rowp;
        const float* trow = next_n_dist + rowt;

        // log p row into shared (51 contiguous floats, 2 coalesced loads)
        slog[warp][lane] = __logf(__ldg(&prow[lane]));
        if (lane < NA - 32)
            slog[warp][lane + 32] = __logf(__ldg(&prow[lane + 32]));
        __syncwarp();

        // Scatter->gather rewrite:
        // td_err = -sum_j td[j] * ((u-b)*logp[l] + (b-l)*logp[u])
        #pragma unroll
        for (int it = 0; it < 2; it++) {
            const int j = lane + it * 32;
            if (j < NA) {
                const float td = __ldg(&trow[j]);
                float tz = r + gTnd * (v_min + dz * (float)j);
                tz = fminf(fmaxf(tz, v_min), v_max);
                float bb = (tz - v_min) * inv_dz;
                bb = fminf(fmaxf(bb, 0.0f), (float)(NA - 1));
                int l = (int)floorf(bb);
                int u = (int)ceilf(bb);
                // disappearing-mass fix (sequential, matches reference)
                if (u > 0 && l == u) l--;
                if (l < NA - 1 && l == u) u++;
                acc += td * ((float)u - bb) * slog[warp][l]
                     + td * (bb - (float)l) * slog[warp][u];
            }
        }

        // warp reduce over atoms
        #pragma unroll
        for (int o = 16; o; o >>= 1)
            acc += __shfl_xor_sync(0xffffffffu, acc, o);

        if (lane == 0) {
            const float tderr = -acc;
            s_td[warp] = tderr;
            s_w[warp]  = tderr * __ldg(&weight[b]);
        }
    } else if (lane == 0) {
        s_td[warp] = 0.0f;
        s_w[warp]  = 0.0f;
    }
    __syncthreads();

    // warp 0: coalesced td_err store + per-block partial for the loss
    if (warp == 0) {
        const int b2 = blockIdx.x * 32 + lane;
        if (b2 < B) td_out[b2] = s_td[lane];
        float v = s_w[lane];
        #pragma unroll
        for (int o = 16; o; o >>= 1)
            v += __shfl_xor_sync(0xffffffffu, v, o);
        if (lane == 0) g_partials[blockIdx.x] = v;
    }
}

__global__ void dtd_reduce_kernel(float* __restrict__ out0, int nparts, float invB)
{
    __shared__ float s[32];
    float v = 0.0f;
    for (int i = threadIdx.x; i < nparts; i += blockDim.x)
        v += g_partials[i];
    #pragma unroll
    for (int o = 16; o; o >>= 1)
        v += __shfl_xor_sync(0xffffffffu, v, o);
    if ((threadIdx.x & 31) == 0) s[threadIdx.x >> 5] = v;
    __syncthreads();
    if (threadIdx.x < 32) {
        v = (threadIdx.x < (int)(blockDim.x >> 5)) ? s[threadIdx.x] : 0.0f;
        #pragma unroll
        for (int o = 16; o; o >>= 1)
            v += __shfl_xor_sync(0xffffffffu, v, o);
        if (threadIdx.x == 0) *out0 = v * invB;
    }
}

extern "C" void kernel_launch(void* const* d_in, const int* in_sizes, int n_in,
                              void* d_out, int out_size)
{
    const float*        dist          = (const float*)d_in[0];
    const float*        next_n_dist   = (const float*)d_in[1];
    const int*          action        = (const int*)d_in[2];
    const int*          next_n_action = (const int*)d_in[3];
    const float*        reward        = (const float*)d_in[4];
    const unsigned int* done          = (const unsigned int*)d_in[5];
    const float*        weight        = (const float*)d_in[6];
    const float*        gamma_p       = (const float*)d_in[7];
    const float*        vmin_p        = (const float*)d_in[8];
    const float*        vmax_p        = (const float*)d_in[9];

    const int B = in_sizes[2];                 // from action (B,)
    const int N = in_sizes[0] / (B * NA);      // dist is (B, N, NA)
    const int T = in_sizes[4] / B;             // reward is (T, B)

    float* out = (float*)d_out;
    // Output flatten of (loss, td_err): td_err is the trailing B elements.
    float* td_out = out + (out_size - B);

    const int blocks = (B + 31) / 32;          // one warp per batch element
    dtd_kernel<<<blocks, 1024>>>(dist, next_n_dist, action, next_n_action,
                                 reward, done, weight, gamma_p, vmin_p, vmax_p,
                                 td_out, B, N, T);
    if (out_size > B) {
        dtd_reduce_kernel<<<1, 1024>>>(out, blocks, 1.0f / (float)B);
    }
}

// round 2
// speedup vs baseline: 1.0756x; 1.0756x over previous
#include <cuda_runtime.h>
#include <cuda_bf16.h>

#define NA 51   // n_atom

// Scratch for deterministic single-kernel loss reduction (no cudaMalloc allowed).
__device__ float        g_partials[8192];
__device__ unsigned int g_count = 0;

__global__ __launch_bounds__(256) void dtd_kernel(
    const float* __restrict__ dist,          // (B, N, NA)
    const float* __restrict__ next_n_dist,   // (B, N, NA)
    const int*   __restrict__ action,        // (B,)
    const int*   __restrict__ next_n_action, // (B,)
    const float* __restrict__ reward,        // (T, B)
    const unsigned int* __restrict__ done,   // (B,) 32-bit encoded bool (!=0 works for i32 and f32)
    const float* __restrict__ weight,        // (B,)
    const float* __restrict__ gamma_p,
    const float* __restrict__ vmin_p,
    const float* __restrict__ vmax_p,
    float* __restrict__ out,                 // flattened (loss?, td_err[B])
    int B, int N, int T, int has_loss, int td_off)
{
    __shared__ float s_log[8][4][NA + 1];    // per-warp, per-element log p rows
    __shared__ float s_w[8];
    __shared__ int   s_last;

    const int warp = threadIdx.x >> 5;
    const int lane = threadIdx.x & 31;
    const int b0   = blockIdx.x * 32 + warp * 4;   // 4 batch elements per warp

    const float gamma  = __ldg(gamma_p);
    const float v_min  = __ldg(vmin_p);
    const float v_max  = __ldg(vmax_p);
    const float dz     = (v_max - v_min) * (1.0f / (float)(NA - 1));
    const float inv_dz = (float)(NA - 1) / (v_max - v_min);

    float* __restrict__ td_out = out + td_off;

    // ---- phase 1: issue ALL index loads up front ----
    int   bc[4], a[4], na[4];
    #pragma unroll
    for (int i = 0; i < 4; i++) {
        int b = b0 + i;
        bc[i] = (b < B) ? b : (B - 1);
        a[i]  = __ldg(&action[bc[i]]);
        na[i] = __ldg(&next_n_action[bc[i]]);
    }

    float gnd[4], wt[4], r[4];
    #pragma unroll
    for (int i = 0; i < 4; i++) {
        float acc = 0.0f, gf = 1.0f;
        for (int t = 0; t < T; t++) {
            acc += gf * __ldg(&reward[(long long)t * B + bc[i]]);
            gf *= gamma;
        }
        r[i]   = acc;
        gnd[i] = (__ldg(&done[bc[i]]) != 0u) ? 0.0f : gf;   // gf == gamma^T
        wt[i]  = __ldg(&weight[bc[i]]);
    }

    // ---- phase 2: issue ALL 8 row gathers front-batched (MLP ~16/thread) ----
    float plo[4], phi[4], tlo[4], thi[4];
    #pragma unroll
    for (int i = 0; i < 4; i++) {
        const float* pr = dist        + ((long long)bc[i] * N + a[i])  * NA;
        const float* tr = next_n_dist + ((long long)bc[i] * N + na[i]) * NA;
        plo[i] = __ldg(&pr[lane]);
        phi[i] = (lane < NA - 32) ? __ldg(&pr[lane + 32]) : 1.0f;
        tlo[i] = __ldg(&tr[lane]);
        thi[i] = (lane < NA - 32) ? __ldg(&tr[lane + 32]) : 0.0f;
    }

    // ---- phase 3: logs into per-warp shared ----
    #pragma unroll
    for (int i = 0; i < 4; i++) {
        s_log[warp][i][lane] = __logf(plo[i]);
        if (lane < NA - 32) s_log[warp][i][lane + 32] = __logf(phi[i]);
    }
    __syncwarp();

    // ---- phase 4: scatter->gather projection + per-warp reductions ----
    // td_err = -sum_j td[j] * ((u-b)*logp[l] + (b-l)*logp[u])
    float wsum = 0.0f;
    #pragma unroll
    for (int i = 0; i < 4; i++) {
        float acc = 0.0f;
        #pragma unroll
        for (int it = 0; it < 2; it++) {
            const int j = lane + it * 32;
            if (j < NA) {
                const float td = (it == 0) ? tlo[i] : thi[i];
                float tz = r[i] + gnd[i] * (v_min + dz * (float)j);
                tz = fminf(fmaxf(tz, v_min), v_max);
                float bb = (tz - v_min) * inv_dz;
                bb = fminf(fmaxf(bb, 0.0f), (float)(NA - 1));
                int l = (int)floorf(bb);
                int u = (int)ceilf(bb);
                if (u > 0 && l == u) l--;          // sequential mass fix
                if (l < NA - 1 && l == u) u++;     // (matches reference)
                acc += td * ((float)u - bb) * s_log[warp][i][l]
                     + td * (bb - (float)l) * s_log[warp][i][u];
            }
        }
        #pragma unroll
        for (int o = 16; o; o >>= 1)
            acc += __shfl_xor_sync(0xffffffffu, acc, o);
        if (lane == 0 && b0 + i < B) {
            const float tderr = -acc;
            td_out[b0 + i] = tderr;
            wsum += tderr * wt[i];
        }
    }

    if (lane == 0) s_w[warp] = wsum;
    __syncthreads();

    // ---- phase 5: block partial + last-block loss reduction (deterministic) ----
    if (threadIdx.x == 0) {
        float v = 0.0f;
        #pragma unroll
        for (int w = 0; w < 8; w++) v += s_w[w];
        g_partials[blockIdx.x] = v;
        __threadfence();
        unsigned int ticket = atomicAdd(&g_count, 1u);
        s_last = (ticket == gridDim.x - 1) ? 1 : 0;
    }
    __syncthreads();

    if (s_last) {
        __threadfence();
        float v = 0.0f;
        const volatile float* gp = g_partials;
        for (int i = threadIdx.x; i < (int)gridDim.x; i += blockDim.x)
            v += gp[i];
        #pragma unroll
        for (int o = 16; o; o >>= 1)
            v += __shfl_xor_sync(0xffffffffu, v, o);
        if (lane == 0) s_w[warp] = v;
        __syncthreads();
        if (threadIdx.x < 32) {
            v = (lane < 8) ? s_w[lane] : 0.0f;
            #pragma unroll
            for (int o = 4; o; o >>= 1)
                v += __shfl_xor_sync(0xffffffffu, v, o);
            if (threadIdx.x == 0) {
                if (has_loss) out[0] = v * (1.0f / (float)B);
                g_count = 0;                        // reset for next graph replay
            }
        }
    }
}

extern "C" void kernel_launch(void* const* d_in, const int* in_sizes, int n_in,
                              void* d_out, int out_size)
{
    const float*        dist          = (const float*)d_in[0];
    const float*        next_n_dist   = (const float*)d_in[1];
    const int*          action        = (const int*)d_in[2];
    const int*          next_n_action = (const int*)d_in[3];
    const float*        reward        = (const float*)d_in[4];
    const unsigned int* done          = (const unsigned int*)d_in[5];
    const float*        weight        = (const float*)d_in[6];
    const float*        gamma_p       = (const float*)d_in[7];
    const float*        vmin_p        = (const float*)d_in[8];
    const float*        vmax_p        = (const float*)d_in[9];

    const int B = in_sizes[2];                 // action is (B,)
    const int N = in_sizes[0] / (B * NA);      // dist is (B, N, NA)
    const int T = in_sizes[4] / B;             // reward is (T, B)

    float* out = (float*)d_out;
    const int td_off   = out_size - B;         // td_err is the trailing B elements
    const int has_loss = (out_size > B) ? 1 : 0;

    const int blocks = (B + 31) / 32;          // 32 batch elements per 256-thread block
    dtd_kernel<<<blocks, 256>>>(dist, next_n_dist, action, next_n_action,
                                reward, done, weight, gamma_p, vmin_p, vmax_p,
                                out, B, N, T, has_loss, td_off);
}

// round 3
// speedup vs baseline: 1.5209x; 1.4140x over previous
#include <cuda_runtime.h>
#include <cuda_bf16.h>

#define NA 51   // n_atom

// Scratch for deterministic single-kernel loss reduction (no cudaMalloc allowed).
__device__ float        g_partials[8192];
__device__ unsigned int g_count = 0;

__global__ __launch_bounds__(256) void dtd_kernel(
    const float* __restrict__ dist,          // (B, N, NA)
    const float* __restrict__ next_n_dist,   // (B, N, NA)
    const int*   __restrict__ action,        // (B,)
    const int*   __restrict__ next_n_action, // (B,)
    const float* __restrict__ reward,        // (T, B)
    const unsigned int* __restrict__ done,   // (B,) 32-bit bool encoding (!=0 works for i32/f32)
    const float* __restrict__ weight,        // (B,)
    const float* __restrict__ gamma_p,
    const float* __restrict__ vmin_p,
    const float* __restrict__ vmax_p,
    float* __restrict__ out,                 // flattened (loss?, td_err[B])
    int B, int N, int T, int has_loss, int td_off)
{
    __shared__ float s_log[8][4][NA + 1];
    __shared__ float s_w[8];
    __shared__ int   s_last;

    const int warp = threadIdx.x >> 5;
    const int lane = threadIdx.x & 31;
    const int b0   = blockIdx.x * 32 + warp * 4;   // 4 batch elements per warp

    const float gamma  = __ldg(gamma_p);
    const float v_min  = __ldg(vmin_p);
    const float v_max  = __ldg(vmax_p);
    const float dz     = (v_max - v_min) * (1.0f / (float)(NA - 1));
    const float inv_dz = (float)(NA - 1) / (v_max - v_min);

    float* __restrict__ td_out = out + td_off;

    // ---- scalar per-element loads (broadcast, warp-uniform per i) ----
    int  bc[4], a[4], na[4];
    bool dn[4];
    float wt[4];
    #pragma unroll
    for (int i = 0; i < 4; i++) {
        bc[i] = min(b0 + i, B - 1);
        a[i]  = __ldg(&action[bc[i]]);
        na[i] = __ldg(&next_n_action[bc[i]]);
        dn[i] = (__ldg(&done[bc[i]]) != 0u);
        wt[i] = __ldg(&weight[bc[i]]);
    }

    // ---- n-step return: lanes 0..3 each own one element, then broadcast ----
    float rv = 0.0f;
    {
        const int bl = min(b0 + lane, B - 1);
        if (lane < 4) {
            float gf = 1.0f;
            for (int t = 0; t < T; t++) {
                rv = fmaf(gf, __ldg(&reward[t * B + bl]), rv);
                gf *= gamma;
            }
        }
    }
    float r[4];
    #pragma unroll
    for (int i = 0; i < 4; i++) r[i] = __shfl_sync(0xffffffffu, rv, i);

    float gT = 1.0f;                           // gamma^T (exact serial multiply)
    for (int t = 0; t < T; t++) gT *= gamma;

    // ---- row gathers: dist rows always; next_n_dist rows only if not done ----
    float plo[4], phi[4], tlo[4], thi[4];
    #pragma unroll
    for (int i = 0; i < 4; i++) {
        const unsigned op = (unsigned)(bc[i] * N + a[i]) * NA;
        plo[i] = __ldg(&dist[op + lane]);
        phi[i] = (lane < NA - 32) ? __ldg(&dist[op + lane + 32]) : 1.0f;
    }
    #pragma unroll
    for (int i = 0; i < 4; i++) {
        tlo[i] = 0.0f; thi[i] = 0.0f;
        if (!dn[i]) {                          // warp-uniform branch
            const unsigned ot = (unsigned)(bc[i] * N + na[i]) * NA;
            tlo[i] = __ldg(&next_n_dist[ot + lane]);
            thi[i] = (lane < NA - 32) ? __ldg(&next_n_dist[ot + lane + 32]) : 0.0f;
        }
    }

    // ---- logs into per-warp shared ----
    #pragma unroll
    for (int i = 0; i < 4; i++) {
        s_log[warp][i][lane] = __logf(plo[i]);
        if (lane < NA - 32) s_log[warp][i][lane + 32] = __logf(phi[i]);
    }
    __syncwarp();

    const float z0 = v_min + dz * (float)lane;
    const float z1 = v_min + dz * (float)(lane + 32);
    const float fNAm1 = (float)(NA - 1);

    float wsum = 0.0f;
    #pragma unroll
    for (int i = 0; i < 4; i++) {
        const float* sl = s_log[warp][i];
        float tderr;
        if (dn[i]) {
            // target_z identical for all atoms; sum(td)=1 -> single interpolation
            float tz = fminf(fmaxf(r[i], v_min), v_max);
            float bb = fminf(fmaxf((tz - v_min) * inv_dz, 0.0f), fNAm1);
            int   l  = max(__float2int_ru(bb) - 1, 0);      // u == l+1 always
            float fl = (float)l;
            tderr = -(((fl + 1.0f) - bb) * sl[l] + (bb - fl) * sl[l + 1]);
        } else {
            float acc;
            {   // atom j = lane
                float tz = fminf(fmaxf(fmaf(gT, z0, r[i]), v_min), v_max);
                float bb = fminf(fmaxf((tz - v_min) * inv_dz, 0.0f), fNAm1);
                int   l  = max(__float2int_ru(bb) - 1, 0);
                float fl = (float)l;
                acc = tlo[i] * (((fl + 1.0f) - bb) * sl[l] + (bb - fl) * sl[l + 1]);
            }
            if (lane < NA - 32) {   // atom j = lane + 32
                float tz = fminf(fmaxf(fmaf(gT, z1, r[i]), v_min), v_max);
                float bb = fminf(fmaxf((tz - v_min) * inv_dz, 0.0f), fNAm1);
                int   l  = max(__float2int_ru(bb) - 1, 0);
                float fl = (float)l;
                acc += thi[i] * (((fl + 1.0f) - bb) * sl[l] + (bb - fl) * sl[l + 1]);
            }
            #pragma unroll
            for (int o = 16; o; o >>= 1)
                acc += __shfl_xor_sync(0xffffffffu, acc, o);
            tderr = -acc;
        }
        if (lane == 0 && b0 + i < B) {
            td_out[b0 + i] = tderr;
            wsum += tderr * wt[i];
        }
    }

    if (lane == 0) s_w[warp] = wsum;
    __syncthreads();

    // ---- block partial + last-block deterministic loss reduction ----
    if (threadIdx.x == 0) {
        float v = 0.0f;
        #pragma unroll
        for (int w = 0; w < 8; w++) v += s_w[w];
        g_partials[blockIdx.x] = v;
        __threadfence();
        unsigned int ticket = atomicAdd(&g_count, 1u);
        s_last = (ticket == gridDim.x - 1) ? 1 : 0;
    }
    __syncthreads();

    if (s_last) {
        __threadfence();
        float v = 0.0f;
        const volatile float* gp = g_partials;
        for (int i = threadIdx.x; i < (int)gridDim.x; i += blockDim.x)
            v += gp[i];
        #pragma unroll
        for (int o = 16; o; o >>= 1)
            v += __shfl_xor_sync(0xffffffffu, v, o);
        if (lane == 0) s_w[warp] = v;
        __syncthreads();
        if (threadIdx.x < 32) {
            v = (lane < 8) ? s_w[lane] : 0.0f;
            #pragma unroll
            for (int o = 4; o; o >>= 1)
                v += __shfl_xor_sync(0xffffffffu, v, o);
            if (threadIdx.x == 0) {
                if (has_loss) out[0] = v * (1.0f / (float)B);
                g_count = 0;                    // reset for next graph replay
            }
        }
    }
}

extern "C" void kernel_launch(void* const* d_in, const int* in_sizes, int n_in,
                              void* d_out, int out_size)
{
    const float*        dist          = (const float*)d_in[0];
    const float*        next_n_dist   = (const float*)d_in[1];
    const int*          action        = (const int*)d_in[2];
    const int*          next_n_action = (const int*)d_in[3];
    const float*        reward        = (const float*)d_in[4];
    const unsigned int* done          = (const unsigned int*)d_in[5];
    const float*        weight        = (const float*)d_in[6];
    const float*        gamma_p       = (const float*)d_in[7];
    const float*        vmin_p        = (const float*)d_in[8];
    const float*        vmax_p        = (const float*)d_in[9];

    const int B = in_sizes[2];                 // action is (B,)
    const int N = in_sizes[0] / (B * NA);      // dist is (B, N, NA)
    const int T = in_sizes[4] / B;             // reward is (T, B)

    float* out = (float*)d_out;
    const int td_off   = out_size - B;         // td_err is the trailing B elements
    const int has_loss = (out_size > B) ? 1 : 0;

    const int blocks = (B + 31) / 32;          // 32 batch elements per 256-thread block
    dtd_kernel<<<blocks, 256>>>(dist, next_n_dist, action, next_n_action,
                                reward, done, weight, gamma_p, vmin_p, vmax_p,
                                out, B, N, T, has_loss, td_off);
}